// round 14
// baseline (speedup 1.0000x reference)
#include <cuda_runtime.h>
#include <cuda_fp16.h>
#include <cstdint>

#define B_SZ 65536
#define K_IN 784
#define N_H  1024
#define N_C  10
#define BN_EPS 1e-5f

#define BM 128
#define BN 256
#define BK 32
#define KPAD 1600
#define NCHUNK (KPAD / BK)        // 50
#define APITCH 40                 // halves per smem row (32 + 8 pad)
#define NSTAGE 5

#define A_STAGE_B (BM * APITCH * 2)           // 10240
#define B_STAGE_B (BN * APITCH * 2)           // 20480
#define SMEM_TOTAL (NSTAGE * (A_STAGE_B + B_STAGE_B))   // 153600
#define NMB (B_SZ / BM)                       // 512 m-blocks

// ---------------- scratch (device globals; no runtime allocation) ----------
__device__ __half g_Ah[(size_t)B_SZ * KPAD];   // [B, 1600] = hi | lo | 0-pad
__device__ __half g_Bh[(size_t)N_H * KPAD];    // [H, 1600] = sign | sign | 0-pad
__device__ float  g_alpha1[N_H];
__device__ float  g_s2a[N_C * N_H];            // alpha2[c] * sign(w2[c][j])
__device__ __half g_d[(size_t)B_SZ * N_H];     // d = x @ sign(w1)^T (fp16)
__device__ float  g_psum[NMB * N_H];
__device__ float  g_psq [NMB * N_H];
__device__ float  g_c1[N_H];
__device__ float  g_c0[N_H];

// ---------------- PTX helpers (baseline ISA only) ----------------------------
__device__ __forceinline__ uint32_t smem_u32(const void* p) {
    uint32_t a;
    asm("{ .reg .u64 t; cvta.to.shared.u64 t, %1; cvt.u32.u64 %0, t; }"
        : "=r"(a) : "l"(p));
    return a;
}
#define CP16(sm, gm) \
    asm volatile("cp.async.cg.shared.global [%0], [%1], 16;" :: "r"(sm), "l"(gm))

__device__ __forceinline__ void ldsm4(uint32_t* r, uint32_t addr) {
    asm volatile("ldmatrix.sync.aligned.m8n8.x4.shared.b16 {%0,%1,%2,%3}, [%4];"
                 : "=r"(r[0]), "=r"(r[1]), "=r"(r[2]), "=r"(r[3]) : "r"(addr));
}
__device__ __forceinline__ void mma16816(float* d, const uint32_t* a,
                                         const uint32_t* b) {
    asm volatile(
        "mma.sync.aligned.m16n8k16.row.col.f32.f16.f16.f32 "
        "{%0,%1,%2,%3}, {%4,%5,%6,%7}, {%8,%9}, {%0,%1,%2,%3};"
        : "+f"(d[0]), "+f"(d[1]), "+f"(d[2]), "+f"(d[3])
        : "r"(a[0]), "r"(a[1]), "r"(a[2]), "r"(a[3]), "r"(b[0]), "r"(b[1]));
}

__device__ __forceinline__ float signf(float w) {
    return (w > 0.f) ? 1.f : ((w < 0.f) ? -1.f : 0.f);
}

// ---------------- x -> (hi, lo) fp16 split (16B stores) ----------------------
__global__ void convert_x(const float* __restrict__ x) {
    size_t i = (size_t)blockIdx.x * 256 + threadIdx.x;   // over B*98 groups of 8
    size_t row = i / 98, g = i % 98;
    const float4* xp = (const float4*)(x + row * K_IN + g * 8);
    float4 v0 = xp[0], v1 = xp[1];
    float f[8] = {v0.x, v0.y, v0.z, v0.w, v1.x, v1.y, v1.z, v1.w};
    __half2 hi[4], lo[4];
    #pragma unroll
    for (int q = 0; q < 4; q++) {
        __half ha = __float2half(f[q * 2]), hb = __float2half(f[q * 2 + 1]);
        hi[q] = __halves2half2(ha, hb);
        lo[q] = __halves2half2(__float2half(f[q * 2]     - __half2float(ha)),
                               __float2half(f[q * 2 + 1] - __half2float(hb)));
    }
    __half* base = g_Ah + row * KPAD;
    *(uint4*)(base + g * 8)       = *(uint4*)hi;
    *(uint4*)(base + 784 + g * 8) = *(uint4*)lo;
    if (g == 0) {
        uint4 z = {0, 0, 0, 0};
        #pragma unroll
        for (int q = 0; q < 4; q++) *(uint4*)(base + 1568 + q * 8) = z;
    }
}

// ---------------- weight prep ------------------------------------------------
__global__ void prep_w1(const float* __restrict__ w1) {
    int n = blockIdx.x;
    const float* row = w1 + n * K_IN;
    __half* brow = g_Bh + (size_t)n * KPAD;
    float s = 0.f;
    for (int k = threadIdx.x; k < K_IN; k += 128) {
        float w = row[k];
        s += fabsf(w);
        __half hs = __float2half(signf(w));
        brow[k] = hs;
        brow[784 + k] = hs;
    }
    if (threadIdx.x < 32) brow[1568 + threadIdx.x] = __float2half(0.f);
    __shared__ float red[128];
    red[threadIdx.x] = s;
    __syncthreads();
    for (int st = 64; st > 0; st >>= 1) {
        if (threadIdx.x < st) red[threadIdx.x] += red[threadIdx.x + st];
        __syncthreads();
    }
    if (threadIdx.x == 0) g_alpha1[n] = red[0] / (float)K_IN;
}

__global__ void prep_w2(const float* __restrict__ w2) {
    __shared__ float a2[N_C];
    int c = threadIdx.x >> 5, l = threadIdx.x & 31;
    if (c < N_C) {
        float s = 0.f;
        for (int j = l; j < N_H; j += 32) s += fabsf(w2[c * N_H + j]);
        #pragma unroll
        for (int o = 16; o; o >>= 1) s += __shfl_down_sync(0xffffffffu, s, o);
        if (l == 0) a2[c] = s / (float)N_H;
    }
    __syncthreads();
    for (int idx = threadIdx.x; idx < N_C * N_H; idx += blockDim.x)
        g_s2a[idx] = a2[idx / N_H] * signf(w2[idx]);
}

// ---------------- HMMA GEMM: d[B, H] = A @ Bh^T + fused BN partials ---------
// CTA 128x256, 512 threads (16 warps: 2 m-slabs x 8 n-slabs), warp tile 64x32.
// BK=32, 5-stage cp.async pipeline, ONE __syncthreads per chunk (R10 config).
// d stored as fp16 (stats from fp32 accumulators).
__global__ __launch_bounds__(512, 1) void gemm1_mma() {
    extern __shared__ char dsm[];
    __half* Abuf = (__half*)dsm;                          // NSTAGE x 128 x 40
    __half* Bbuf = (__half*)(dsm + NSTAGE * A_STAGE_B);   // NSTAGE x 256 x 40

    const int tid  = threadIdx.x;
    const int lane = tid & 31;
    const int w    = tid >> 5;
    const int wm   = w & 1;          // 0..1 : 64-row slab
    const int wn   = w >> 1;         // 0..7 : 32-col slab
    const int bm   = blockIdx.y * BM;
    const int bn   = blockIdx.x * BN;

    float acc[4][4][4];
    #pragma unroll
    for (int i = 0; i < 4; i++)
        #pragma unroll
        for (int j = 0; j < 4; j++)
            #pragma unroll
            for (int q = 0; q < 4; q++) acc[i][j][q] = 0.f;

    // hoisted LDSM base addresses (stage 0, h = 0)
    uint32_t aAddr[4], bAddr[2];
    #pragma unroll
    for (int mi = 0; mi < 4; mi++)
        aAddr[mi] = smem_u32(Abuf + (wm * 64 + mi * 16 + (lane & 15)) * APITCH
                             + (lane >> 4) * 8);
    {
        int g = lane >> 3, r = lane & 7;
        #pragma unroll
        for (int jp = 0; jp < 2; jp++)
            bAddr[jp] = smem_u32(Bbuf + (wn * 32 + jp * 16 + ((g & 2) ? 8 : 0) + r)
                                 * APITCH + (g & 1) * 8);
    }

    // cp.async addressing: A 512 ops (1/thread), B 1024 ops (2/thread)
    const int a_row = tid >> 2;
    const int a_ck  = tid & 3;
    const uint32_t cpA = smem_u32(Abuf + a_row * APITCH + a_ck * 8);
    const int b_r0 = tid >> 2,          b_ck0 = tid & 3;
    const int b_r1 = (tid + 512) >> 2,  b_ck1 = tid & 3;
    const uint32_t cpB0 = smem_u32(Bbuf + b_r0 * APITCH + b_ck0 * 8);
    const uint32_t cpB1 = smem_u32(Bbuf + b_r1 * APITCH + b_ck1 * 8);
    const __half* gA = g_Ah + (size_t)(bm + a_row) * KPAD + a_ck * 8;
    const __half* gB0 = g_Bh + (size_t)(bn + b_r0) * KPAD + b_ck0 * 8;
    const __half* gB1 = g_Bh + (size_t)(bn + b_r1) * KPAD + b_ck1 * 8;

    auto prefetch = [&](int c, uint32_t sA, uint32_t sB) {
        if (c < NCHUNK) {
            const int k0 = c * BK;
            CP16(cpA + sA, gA + k0);
            CP16(cpB0 + sB, gB0 + k0);
            CP16(cpB1 + sB, gB1 + k0);
        }
        asm volatile("cp.async.commit_group;");
    };

    prefetch(0, 0, 0);
    prefetch(1, A_STAGE_B, B_STAGE_B);
    prefetch(2, 2 * A_STAGE_B, 2 * B_STAGE_B);
    prefetch(3, 3 * A_STAGE_B, 3 * B_STAGE_B);

    uint32_t sA = 0, sB = 0;                          // stage of chunk c
    uint32_t pA = 4 * A_STAGE_B, pB = 4 * B_STAGE_B;  // stage of chunk c+4

    for (int c = 0; c < NCHUNK; c++) {
        asm volatile("cp.async.wait_group 3;" ::: "memory");
        __syncthreads();

        // h0 fragments first so the first MMA's deps land earliest
        uint32_t afr[4][4];
        #pragma unroll
        for (int mi = 0; mi < 4; mi++) ldsm4(afr[mi], aAddr[mi] + sA);
        uint32_t bfr[2][4][2];
        #pragma unroll
        for (int jp = 0; jp < 2; jp++) {
            uint32_t rr[4];
            ldsm4(rr, bAddr[jp] + sB);
            bfr[0][jp * 2 + 0][0] = rr[0]; bfr[0][jp * 2 + 0][1] = rr[1];
            bfr[0][jp * 2 + 1][0] = rr[2]; bfr[0][jp * 2 + 1][1] = rr[3];
        }
        prefetch(c + 4, pA, pB);
        #pragma unroll
        for (int mi = 0; mi < 4; mi++)
            #pragma unroll
            for (int ni = 0; ni < 4; ni++)
                mma16816(acc[mi][ni], afr[mi], bfr[0][ni]);

        #pragma unroll
        for (int jp = 0; jp < 2; jp++) {
            uint32_t rr[4];
            ldsm4(rr, bAddr[jp] + sB + 32);
            bfr[1][jp * 2 + 0][0] = rr[0]; bfr[1][jp * 2 + 0][1] = rr[1];
            bfr[1][jp * 2 + 1][0] = rr[2]; bfr[1][jp * 2 + 1][1] = rr[3];
        }
        #pragma unroll
        for (int mi = 0; mi < 4; mi++) ldsm4(afr[mi], aAddr[mi] + sA + 32);
        #pragma unroll
        for (int mi = 0; mi < 4; mi++)
            #pragma unroll
            for (int ni = 0; ni < 4; ni++)
                mma16816(acc[mi][ni], afr[mi], bfr[1][ni]);

        // ring advance: both cursors move one stage per iteration
        sA += A_STAGE_B; if (sA == NSTAGE * A_STAGE_B) sA = 0;
        sB += B_STAGE_B; if (sB == NSTAGE * B_STAGE_B) sB = 0;
        pA += A_STAGE_B; if (pA == NSTAGE * A_STAGE_B) pA = 0;
        pB += B_STAGE_B; if (pB == NSTAGE * B_STAGE_B) pB = 0;
    }

    // ---- epilogue 1: store d tile as fp16 -------------------------------
    __half* base = g_d + (size_t)(bm + wm * 64) * N_H + bn + wn * 32;
    #pragma unroll
    for (int mi = 0; mi < 4; mi++) {
        #pragma unroll
        for (int ni = 0; ni < 4; ni++) {
            int r0  = mi * 16 + (lane >> 2);
            int col = ni * 8 + (lane & 3) * 2;
            __half2 v0 = __floats2half2_rn(acc[mi][ni][0], acc[mi][ni][1]);
            __half2 v1 = __floats2half2_rn(acc[mi][ni][2], acc[mi][ni][3]);
            *(__half2*)(base + (size_t)r0 * N_H + col)       = v0;
            *(__half2*)(base + (size_t)(r0 + 8) * N_H + col) = v1;
        }
    }

    // ---- epilogue 2: fused BN partial sums (fp32 acc, deterministic) ----
    float cs[8], cq[8];
    #pragma unroll
    for (int ni = 0; ni < 4; ni++) {
        #pragma unroll
        for (int q = 0; q < 2; q++) {
            float s = 0.f, sq = 0.f;
            #pragma unroll
            for (int mi = 0; mi < 4; mi++) {
                float v0 = acc[mi][ni][q], v1 = acc[mi][ni][q + 2];
                s += v0 + v1;
                sq = fmaf(v0, v0, sq);
                sq = fmaf(v1, v1, sq);
            }
            cs[ni * 2 + q] = s;
            cq[ni * 2 + q] = sq;
        }
    }
    #pragma unroll
    for (int o = 4; o <= 16; o <<= 1) {
        #pragma unroll
        for (int t = 0; t < 8; t++) {
            cs[t] += __shfl_xor_sync(0xffffffffu, cs[t], o);
            cq[t] += __shfl_xor_sync(0xffffffffu, cq[t], o);
        }
    }
    __syncthreads();                       // pipeline smem no longer needed
    float* sS = (float*)dsm;               // [2][256]
    float* sQ = sS + 512;                  // [2][256]
    if (lane < 4) {
        #pragma unroll
        for (int ni = 0; ni < 4; ni++) {
            #pragma unroll
            for (int q = 0; q < 2; q++) {
                int colL = wn * 32 + ni * 8 + lane * 2 + q;
                sS[wm * 256 + colL] = cs[ni * 2 + q];
                sQ[wm * 256 + colL] = cq[ni * 2 + q];
            }
        }
    }
    __syncthreads();
    if (tid < 256) {
        float s  = sS[tid] + sS[256 + tid];
        float sq = sQ[tid] + sQ[256 + tid];
        g_psum[(size_t)blockIdx.y * N_H + bn + tid] = s;
        g_psq [(size_t)blockIdx.y * N_H + bn + tid] = sq;
    }
}

// ---------------- BN stats finalize: one block per column -------------------
__global__ void stats_final(const float* __restrict__ gamma,
                            const float* __restrict__ beta) {
    int j = blockIdx.x;                       // 1024 blocks
    int t = threadIdx.x;                      // 128 threads
    __shared__ float rs[128], rq[128];
    float s = 0.f, q = 0.f;
    for (int p = t; p < NMB; p += 128) {      // fixed order -> deterministic
        s += g_psum[(size_t)p * N_H + j];
        q += g_psq [(size_t)p * N_H + j];
    }
    rs[t] = s; rq[t] = q;
    __syncthreads();
    for (int st = 64; st > 0; st >>= 1) {
        if (t < st) { rs[t] += rs[t + st]; rq[t] += rq[t + st]; }
        __syncthreads();
    }
    if (t == 0) {
        float inv = 1.f / (float)B_SZ;
        float mu  = rs[0] * inv;
        float var = rq[0] * inv - mu * mu;
        float a1  = g_alpha1[j];
        float r   = rsqrtf(a1 * a1 * var + BN_EPS);
        float c1  = gamma[j] * a1 * r;
        g_c1[j] = c1;
        g_c0[j] = beta[j] - c1 * mu;
    }
}

// ---------------- fused sign + GEMM2 (warp does 4 rows; fp16 d) -------------
__global__ __launch_bounds__(256) void final_k(float* __restrict__ out) {
    __shared__ float s2[N_C][N_H];
    __shared__ float c1s[N_H];
    __shared__ float c0s[N_H];
    for (int i = threadIdx.x; i < N_C * N_H; i += 256) ((float*)s2)[i] = g_s2a[i];
    for (int i = threadIdx.x; i < N_H; i += 256) {
        c1s[i] = g_c1[i];
        c0s[i] = g_c0[i];
    }
    __syncthreads();

    int w = threadIdx.x >> 5, l = threadIdx.x & 31;
    #pragma unroll
    for (int r = 0; r < 4; r++) {
        int row = blockIdx.x * 32 + w * 4 + r;
        const __half2* dr = (const __half2*)(g_d + (size_t)row * N_H);

        float acc[N_C];
        #pragma unroll
        for (int c = 0; c < N_C; c++) acc[c] = 0.f;

        for (int g = 0; g < 16; g++) {
            int col = g * 64 + l * 2;
            float2 v = __half22float2(dr[col >> 1]);
            float s0 = c1s[col]     * v.x + c0s[col];
            float s1 = c1s[col + 1] * v.y + c0s[col + 1];
            float a0 = (s0 > 0.f) ? 1.f : ((s0 < 0.f) ? -1.f : 0.f);
            float a1 = (s1 > 0.f) ? 1.f : ((s1 < 0.f) ? -1.f : 0.f);
            #pragma unroll
            for (int c = 0; c < N_C; c++) {
                acc[c] = fmaf(a0, s2[c][col], acc[c]);
                acc[c] = fmaf(a1, s2[c][col + 1], acc[c]);
            }
        }
        #pragma unroll
        for (int c = 0; c < N_C; c++) {
            float v = acc[c];
            #pragma unroll
            for (int o = 16; o; o >>= 1) v += __shfl_down_sync(0xffffffffu, v, o);
            if (l == 0) out[(size_t)row * N_C + c] = v;
        }
    }
}

// ---------------- launch -----------------------------------------------------
extern "C" void kernel_launch(void* const* d_in, const int* in_sizes, int n_in,
                              void* d_out, int out_size) {
    const float* x     = (const float*)d_in[0];
    const float* w1    = (const float*)d_in[1];
    const float* w2    = (const float*)d_in[2];
    const float* gamma = (const float*)d_in[3];
    const float* beta  = (const float*)d_in[4];
    float* out = (float*)d_out;

    cudaFuncSetAttribute(gemm1_mma, cudaFuncAttributeMaxDynamicSharedMemorySize,
                         SMEM_TOTAL);

    convert_x<<<(B_SZ * 98) / 256, 256>>>(x);
    prep_w1<<<N_H, 128>>>(w1);
    prep_w2<<<1, 320>>>(w2);
    gemm1_mma<<<dim3(N_H / BN, B_SZ / BM), 512, SMEM_TOTAL>>>();
    stats_final<<<N_H, 128>>>(gamma, beta);
    final_k<<<B_SZ / 32, 256>>>(out);
}

// round 15
// speedup vs baseline: 1.0032x; 1.0032x over previous
#include <cuda_runtime.h>
#include <cuda_fp16.h>
#include <cstdint>

#define B_SZ 65536
#define K_IN 784
#define N_H  1024
#define N_C  10
#define BN_EPS 1e-5f

#define BM 128
#define BN 256
#define BK 32
#define KPAD 1600
#define NCHUNK (KPAD / BK)        // 50
#define APITCH 40                 // halves per smem row (32 + 8 pad)
#define NSTAGE 5

#define A_STAGE_B (BM * APITCH * 2)           // 10240
#define B_STAGE_B (BN * APITCH * 2)           // 20480
#define SMEM_TOTAL (NSTAGE * (A_STAGE_B + B_STAGE_B))   // 153600
#define NMB (B_SZ / BM)                       // 512 m-blocks

// ---------------- scratch (device globals; no runtime allocation) ----------
__device__ __half g_Ah[(size_t)B_SZ * KPAD];   // [B, 1600] = hi | lo | 0-pad
__device__ __half g_Bh[(size_t)N_H * KPAD];    // [H, 1600] = sign | sign | 0-pad
__device__ float  g_alpha1[N_H];
__device__ float  g_s2a[N_C * N_H];            // alpha2[c] * sign(w2[c][j])
__device__ __half g_d[(size_t)B_SZ * N_H];     // d = x @ sign(w1)^T (fp16)
__device__ float  g_psum[NMB * N_H];
__device__ float  g_psq [NMB * N_H];
__device__ float  g_c1[N_H];
__device__ float  g_c0[N_H];

// ---------------- PTX helpers (baseline ISA only) ----------------------------
__device__ __forceinline__ uint32_t smem_u32(const void* p) {
    uint32_t a;
    asm("{ .reg .u64 t; cvta.to.shared.u64 t, %1; cvt.u32.u64 %0, t; }"
        : "=r"(a) : "l"(p));
    return a;
}
#define CP16(sm, gm) \
    asm volatile("cp.async.cg.shared.global [%0], [%1], 16;" :: "r"(sm), "l"(gm))

__device__ __forceinline__ void ldsm4(uint32_t* r, uint32_t addr) {
    asm volatile("ldmatrix.sync.aligned.m8n8.x4.shared.b16 {%0,%1,%2,%3}, [%4];"
                 : "=r"(r[0]), "=r"(r[1]), "=r"(r[2]), "=r"(r[3]) : "r"(addr));
}
__device__ __forceinline__ void mma16816(float* d, const uint32_t* a,
                                         const uint32_t* b) {
    asm volatile(
        "mma.sync.aligned.m16n8k16.row.col.f32.f16.f16.f32 "
        "{%0,%1,%2,%3}, {%4,%5,%6,%7}, {%8,%9}, {%0,%1,%2,%3};"
        : "+f"(d[0]), "+f"(d[1]), "+f"(d[2]), "+f"(d[3])
        : "r"(a[0]), "r"(a[1]), "r"(a[2]), "r"(a[3]), "r"(b[0]), "r"(b[1]));
}

__device__ __forceinline__ float signf(float w) {
    return (w > 0.f) ? 1.f : ((w < 0.f) ? -1.f : 0.f);
}

// ---------------- x -> (hi, lo) fp16 split (16B stores) ----------------------
__global__ void convert_x(const float* __restrict__ x) {
    size_t i = (size_t)blockIdx.x * 256 + threadIdx.x;   // over B*98 groups of 8
    size_t row = i / 98, g = i % 98;
    const float4* xp = (const float4*)(x + row * K_IN + g * 8);
    float4 v0 = xp[0], v1 = xp[1];
    float f[8] = {v0.x, v0.y, v0.z, v0.w, v1.x, v1.y, v1.z, v1.w};
    __half2 hi[4], lo[4];
    #pragma unroll
    for (int q = 0; q < 4; q++) {
        __half ha = __float2half(f[q * 2]), hb = __float2half(f[q * 2 + 1]);
        hi[q] = __halves2half2(ha, hb);
        lo[q] = __halves2half2(__float2half(f[q * 2]     - __half2float(ha)),
                               __float2half(f[q * 2 + 1] - __half2float(hb)));
    }
    __half* base = g_Ah + row * KPAD;
    *(uint4*)(base + g * 8)       = *(uint4*)hi;
    *(uint4*)(base + 784 + g * 8) = *(uint4*)lo;
    if (g == 0) {
        uint4 z = {0, 0, 0, 0};
        #pragma unroll
        for (int q = 0; q < 4; q++) *(uint4*)(base + 1568 + q * 8) = z;
    }
}

// ---------------- weight prep ------------------------------------------------
__global__ void prep_w1(const float* __restrict__ w1) {
    int n = blockIdx.x;
    const float* row = w1 + n * K_IN;
    __half* brow = g_Bh + (size_t)n * KPAD;
    float s = 0.f;
    for (int k = threadIdx.x; k < K_IN; k += 128) {
        float w = row[k];
        s += fabsf(w);
        __half hs = __float2half(signf(w));
        brow[k] = hs;
        brow[784 + k] = hs;
    }
    if (threadIdx.x < 32) brow[1568 + threadIdx.x] = __float2half(0.f);
    __shared__ float red[128];
    red[threadIdx.x] = s;
    __syncthreads();
    for (int st = 64; st > 0; st >>= 1) {
        if (threadIdx.x < st) red[threadIdx.x] += red[threadIdx.x + st];
        __syncthreads();
    }
    if (threadIdx.x == 0) g_alpha1[n] = red[0] / (float)K_IN;
}

__global__ void prep_w2(const float* __restrict__ w2) {
    __shared__ float a2[N_C];
    int c = threadIdx.x >> 5, l = threadIdx.x & 31;
    if (c < N_C) {
        float s = 0.f;
        for (int j = l; j < N_H; j += 32) s += fabsf(w2[c * N_H + j]);
        #pragma unroll
        for (int o = 16; o; o >>= 1) s += __shfl_down_sync(0xffffffffu, s, o);
        if (l == 0) a2[c] = s / (float)N_H;
    }
    __syncthreads();
    for (int idx = threadIdx.x; idx < N_C * N_H; idx += blockDim.x)
        g_s2a[idx] = a2[idx / N_H] * signf(w2[idx]);
}

// ---------------- HMMA GEMM: d[B, H] = A @ Bh^T + fused BN partials ---------
// CTA 128x256, 512 threads (16 warps: 2 m-slabs x 8 n-slabs), warp tile 64x32.
// BK=32, 5-stage cp.async pipeline, ONE __syncthreads per chunk (R10 config).
// d stored as fp16 (stats from fp32 accumulators).
__global__ __launch_bounds__(512, 1) void gemm1_mma() {
    extern __shared__ char dsm[];
    __half* Abuf = (__half*)dsm;                          // NSTAGE x 128 x 40
    __half* Bbuf = (__half*)(dsm + NSTAGE * A_STAGE_B);   // NSTAGE x 256 x 40

    const int tid  = threadIdx.x;
    const int lane = tid & 31;
    const int w    = tid >> 5;
    const int wm   = w & 1;          // 0..1 : 64-row slab
    const int wn   = w >> 1;         // 0..7 : 32-col slab
    const int bm   = blockIdx.y * BM;
    const int bn   = blockIdx.x * BN;

    float acc[4][4][4];
    #pragma unroll
    for (int i = 0; i < 4; i++)
        #pragma unroll
        for (int j = 0; j < 4; j++)
            #pragma unroll
            for (int q = 0; q < 4; q++) acc[i][j][q] = 0.f;

    // hoisted LDSM base addresses (stage 0, h = 0)
    uint32_t aAddr[4], bAddr[2];
    #pragma unroll
    for (int mi = 0; mi < 4; mi++)
        aAddr[mi] = smem_u32(Abuf + (wm * 64 + mi * 16 + (lane & 15)) * APITCH
                             + (lane >> 4) * 8);
    {
        int g = lane >> 3, r = lane & 7;
        #pragma unroll
        for (int jp = 0; jp < 2; jp++)
            bAddr[jp] = smem_u32(Bbuf + (wn * 32 + jp * 16 + ((g & 2) ? 8 : 0) + r)
                                 * APITCH + (g & 1) * 8);
    }

    // cp.async addressing: A 512 ops (1/thread), B 1024 ops (2/thread)
    const int a_row = tid >> 2;
    const int a_ck  = tid & 3;
    const uint32_t cpA = smem_u32(Abuf + a_row * APITCH + a_ck * 8);
    const int b_r0 = tid >> 2,          b_ck0 = tid & 3;
    const int b_r1 = (tid + 512) >> 2,  b_ck1 = tid & 3;
    const uint32_t cpB0 = smem_u32(Bbuf + b_r0 * APITCH + b_ck0 * 8);
    const uint32_t cpB1 = smem_u32(Bbuf + b_r1 * APITCH + b_ck1 * 8);
    const __half* gA = g_Ah + (size_t)(bm + a_row) * KPAD + a_ck * 8;
    const __half* gB0 = g_Bh + (size_t)(bn + b_r0) * KPAD + b_ck0 * 8;
    const __half* gB1 = g_Bh + (size_t)(bn + b_r1) * KPAD + b_ck1 * 8;

    auto prefetch = [&](int c, uint32_t sA, uint32_t sB) {
        if (c < NCHUNK) {
            const int k0 = c * BK;
            CP16(cpA + sA, gA + k0);
            CP16(cpB0 + sB, gB0 + k0);
            CP16(cpB1 + sB, gB1 + k0);
        }
        asm volatile("cp.async.commit_group;");
    };

    prefetch(0, 0, 0);
    prefetch(1, A_STAGE_B, B_STAGE_B);
    prefetch(2, 2 * A_STAGE_B, 2 * B_STAGE_B);
    prefetch(3, 3 * A_STAGE_B, 3 * B_STAGE_B);

    uint32_t sA = 0, sB = 0;                          // stage of chunk c
    uint32_t pA = 4 * A_STAGE_B, pB = 4 * B_STAGE_B;  // stage of chunk c+4

    for (int c = 0; c < NCHUNK; c++) {
        asm volatile("cp.async.wait_group 3;" ::: "memory");
        __syncthreads();

        // h0 fragments first so the first MMA's deps land earliest
        uint32_t afr[4][4];
        #pragma unroll
        for (int mi = 0; mi < 4; mi++) ldsm4(afr[mi], aAddr[mi] + sA);
        uint32_t bfr[2][4][2];
        #pragma unroll
        for (int jp = 0; jp < 2; jp++) {
            uint32_t rr[4];
            ldsm4(rr, bAddr[jp] + sB);
            bfr[0][jp * 2 + 0][0] = rr[0]; bfr[0][jp * 2 + 0][1] = rr[1];
            bfr[0][jp * 2 + 1][0] = rr[2]; bfr[0][jp * 2 + 1][1] = rr[3];
        }
        prefetch(c + 4, pA, pB);
        #pragma unroll
        for (int mi = 0; mi < 4; mi++)
            #pragma unroll
            for (int ni = 0; ni < 4; ni++)
                mma16816(acc[mi][ni], afr[mi], bfr[0][ni]);

        #pragma unroll
        for (int jp = 0; jp < 2; jp++) {
            uint32_t rr[4];
            ldsm4(rr, bAddr[jp] + sB + 32);
            bfr[1][jp * 2 + 0][0] = rr[0]; bfr[1][jp * 2 + 0][1] = rr[1];
            bfr[1][jp * 2 + 1][0] = rr[2]; bfr[1][jp * 2 + 1][1] = rr[3];
        }
        #pragma unroll
        for (int mi = 0; mi < 4; mi++) ldsm4(afr[mi], aAddr[mi] + sA + 32);
        #pragma unroll
        for (int mi = 0; mi < 4; mi++)
            #pragma unroll
            for (int ni = 0; ni < 4; ni++)
                mma16816(acc[mi][ni], afr[mi], bfr[1][ni]);

        // ring advance: both cursors move one stage per iteration
        sA += A_STAGE_B; if (sA == NSTAGE * A_STAGE_B) sA = 0;
        sB += B_STAGE_B; if (sB == NSTAGE * B_STAGE_B) sB = 0;
        pA += A_STAGE_B; if (pA == NSTAGE * A_STAGE_B) pA = 0;
        pB += B_STAGE_B; if (pB == NSTAGE * B_STAGE_B) pB = 0;
    }

    // ---- epilogue 1: store d tile as fp16 -------------------------------
    __half* base = g_d + (size_t)(bm + wm * 64) * N_H + bn + wn * 32;
    #pragma unroll
    for (int mi = 0; mi < 4; mi++) {
        #pragma unroll
        for (int ni = 0; ni < 4; ni++) {
            int r0  = mi * 16 + (lane >> 2);
            int col = ni * 8 + (lane & 3) * 2;
            __half2 v0 = __floats2half2_rn(acc[mi][ni][0], acc[mi][ni][1]);
            __half2 v1 = __floats2half2_rn(acc[mi][ni][2], acc[mi][ni][3]);
            *(__half2*)(base + (size_t)r0 * N_H + col)       = v0;
            *(__half2*)(base + (size_t)(r0 + 8) * N_H + col) = v1;
        }
    }

    // ---- epilogue 2: fused BN partial sums (fp32 acc, deterministic) ----
    float cs[8], cq[8];
    #pragma unroll
    for (int ni = 0; ni < 4; ni++) {
        #pragma unroll
        for (int q = 0; q < 2; q++) {
            float s = 0.f, sq = 0.f;
            #pragma unroll
            for (int mi = 0; mi < 4; mi++) {
                float v0 = acc[mi][ni][q], v1 = acc[mi][ni][q + 2];
                s += v0 + v1;
                sq = fmaf(v0, v0, sq);
                sq = fmaf(v1, v1, sq);
            }
            cs[ni * 2 + q] = s;
            cq[ni * 2 + q] = sq;
        }
    }
    #pragma unroll
    for (int o = 4; o <= 16; o <<= 1) {
        #pragma unroll
        for (int t = 0; t < 8; t++) {
            cs[t] += __shfl_xor_sync(0xffffffffu, cs[t], o);
            cq[t] += __shfl_xor_sync(0xffffffffu, cq[t], o);
        }
    }
    __syncthreads();                       // pipeline smem no longer needed
    float* sS = (float*)dsm;               // [2][256]
    float* sQ = sS + 512;                  // [2][256]
    if (lane < 4) {
        #pragma unroll
        for (int ni = 0; ni < 4; ni++) {
            #pragma unroll
            for (int q = 0; q < 2; q++) {
                int colL = wn * 32 + ni * 8 + lane * 2 + q;
                sS[wm * 256 + colL] = cs[ni * 2 + q];
                sQ[wm * 256 + colL] = cq[ni * 2 + q];
            }
        }
    }
    __syncthreads();
    if (tid < 256) {
        float s  = sS[tid] + sS[256 + tid];
        float sq = sQ[tid] + sQ[256 + tid];
        g_psum[(size_t)blockIdx.y * N_H + bn + tid] = s;
        g_psq [(size_t)blockIdx.y * N_H + bn + tid] = sq;
    }
}

// ---------------- BN stats finalize: one block per column -------------------
__global__ void stats_final(const float* __restrict__ gamma,
                            const float* __restrict__ beta) {
    int j = blockIdx.x;                       // 1024 blocks
    int t = threadIdx.x;                      // 128 threads
    __shared__ float rs[128], rq[128];
    float s = 0.f, q = 0.f;
    for (int p = t; p < NMB; p += 128) {      // fixed order -> deterministic
        s += g_psum[(size_t)p * N_H + j];
        q += g_psq [(size_t)p * N_H + j];
    }
    rs[t] = s; rq[t] = q;
    __syncthreads();
    for (int st = 64; st > 0; st >>= 1) {
        if (t < st) { rs[t] += rs[t + st]; rq[t] += rq[t + st]; }
        __syncthreads();
    }
    if (t == 0) {
        float inv = 1.f / (float)B_SZ;
        float mu  = rs[0] * inv;
        float var = rq[0] * inv - mu * mu;
        float a1  = g_alpha1[j];
        float r   = rsqrtf(a1 * a1 * var + BN_EPS);
        float c1  = gamma[j] * a1 * r;
        g_c1[j] = c1;
        g_c0[j] = beta[j] - c1 * mu;
    }
}

// ---------------- fused sign + GEMM2 (warp does 4 rows; fp16 d) -------------
__global__ __launch_bounds__(256) void final_k(float* __restrict__ out) {
    __shared__ float s2[N_C][N_H];
    __shared__ float c1s[N_H];
    __shared__ float c0s[N_H];
    for (int i = threadIdx.x; i < N_C * N_H; i += 256) ((float*)s2)[i] = g_s2a[i];
    for (int i = threadIdx.x; i < N_H; i += 256) {
        c1s[i] = g_c1[i];
        c0s[i] = g_c0[i];
    }
    __syncthreads();

    int w = threadIdx.x >> 5, l = threadIdx.x & 31;
    #pragma unroll
    for (int r = 0; r < 4; r++) {
        int row = blockIdx.x * 32 + w * 4 + r;
        const __half2* dr = (const __half2*)(g_d + (size_t)row * N_H);

        float acc[N_C];
        #pragma unroll
        for (int c = 0; c < N_C; c++) acc[c] = 0.f;

        for (int g = 0; g < 16; g++) {
            int col = g * 64 + l * 2;
            float2 v = __half22float2(dr[col >> 1]);
            float s0 = c1s[col]     * v.x + c0s[col];
            float s1 = c1s[col + 1] * v.y + c0s[col + 1];
            float a0 = (s0 > 0.f) ? 1.f : ((s0 < 0.f) ? -1.f : 0.f);
            float a1 = (s1 > 0.f) ? 1.f : ((s1 < 0.f) ? -1.f : 0.f);
            #pragma unroll
            for (int c = 0; c < N_C; c++) {
                acc[c] = fmaf(a0, s2[c][col], acc[c]);
                acc[c] = fmaf(a1, s2[c][col + 1], acc[c]);
            }
        }
        #pragma unroll
        for (int c = 0; c < N_C; c++) {
            float v = acc[c];
            #pragma unroll
            for (int o = 16; o; o >>= 1) v += __shfl_down_sync(0xffffffffu, v, o);
            if (l == 0) out[(size_t)row * N_C + c] = v;
        }
    }
}

// ---------------- launch -----------------------------------------------------
extern "C" void kernel_launch(void* const* d_in, const int* in_sizes, int n_in,
                              void* d_out, int out_size) {
    const float* x     = (const float*)d_in[0];
    const float* w1    = (const float*)d_in[1];
    const float* w2    = (const float*)d_in[2];
    const float* gamma = (const float*)d_in[3];
    const float* beta  = (const float*)d_in[4];
    float* out = (float*)d_out;

    cudaFuncSetAttribute(gemm1_mma, cudaFuncAttributeMaxDynamicSharedMemorySize,
                         SMEM_TOTAL);

    convert_x<<<(B_SZ * 98) / 256, 256>>>(x);
    prep_w1<<<N_H, 128>>>(w1);
    prep_w2<<<1, 320>>>(w2);
    gemm1_mma<<<dim3(N_H / BN, B_SZ / BM), 512, SMEM_TOTAL>>>();
    stats_final<<<N_H, 128>>>(gamma, beta);
    final_k<<<B_SZ / 32, 256>>>(out);
}

// round 16
// speedup vs baseline: 1.0132x; 1.0100x over previous
#include <cuda_runtime.h>
#include <cuda_fp16.h>
#include <cstdint>

#define B_SZ 65536
#define K_IN 784
#define N_H  1024
#define N_C  10
#define BN_EPS 1e-5f

#define BM 128
#define BN 256
#define BK 32
#define KPAD 1600
#define NCHUNK (KPAD / BK)        // 50
#define APITCH 40                 // halves per smem row (32 + 8 pad)
#define NSTAGE 5

#define A_STAGE_B (BM * APITCH * 2)           // 10240
#define B_STAGE_B (BN * APITCH * 2)           // 20480
#define SMEM_TOTAL (NSTAGE * (A_STAGE_B + B_STAGE_B))   // 153600
#define NMB (B_SZ / BM)                       // 512 m-blocks

#define CVT_BLOCKS ((B_SZ * 98) / 256)        // 25088 convert blocks
#define PREP_BLOCKS (CVT_BLOCKS + N_H + 1)    // + w1 + w2

// ---------------- scratch (device globals; no runtime allocation) ----------
__device__ __half g_Ah[(size_t)B_SZ * KPAD];   // [B, 1600] = hi | lo | 0-pad
__device__ __half g_Bh[(size_t)N_H * KPAD];    // [H, 1600] = sign | sign | 0-pad
__device__ float  g_alpha1[N_H];
__device__ float  g_s2a[N_C * N_H];            // alpha2[c] * sign(w2[c][j])
__device__ float  g_d[(size_t)B_SZ * N_H];     // d = x @ sign(w1)^T (fp32)
__device__ float  g_psum[NMB * N_H];
__device__ float  g_psq [NMB * N_H];
__device__ float  g_c1[N_H];
__device__ float  g_c0[N_H];

// ---------------- PTX helpers (baseline ISA only) ----------------------------
__device__ __forceinline__ uint32_t smem_u32(const void* p) {
    uint32_t a;
    asm("{ .reg .u64 t; cvta.to.shared.u64 t, %1; cvt.u32.u64 %0, t; }"
        : "=r"(a) : "l"(p));
    return a;
}
#define CP16(sm, gm) \
    asm volatile("cp.async.cg.shared.global [%0], [%1], 16;" :: "r"(sm), "l"(gm))

__device__ __forceinline__ void ldsm4(uint32_t* r, uint32_t addr) {
    asm volatile("ldmatrix.sync.aligned.m8n8.x4.shared.b16 {%0,%1,%2,%3}, [%4];"
                 : "=r"(r[0]), "=r"(r[1]), "=r"(r[2]), "=r"(r[3]) : "r"(addr));
}
__device__ __forceinline__ void mma16816(float* d, const uint32_t* a,
                                         const uint32_t* b) {
    asm volatile(
        "mma.sync.aligned.m16n8k16.row.col.f32.f16.f16.f32 "
        "{%0,%1,%2,%3}, {%4,%5,%6,%7}, {%8,%9}, {%0,%1,%2,%3};"
        : "+f"(d[0]), "+f"(d[1]), "+f"(d[2]), "+f"(d[3])
        : "r"(a[0]), "r"(a[1]), "r"(a[2]), "r"(a[3]), "r"(b[0]), "r"(b[1]));
}

__device__ __forceinline__ float signf(float w) {
    return (w > 0.f) ? 1.f : ((w < 0.f) ? -1.f : 0.f);
}

// ---------------- fused prep: x split + w1 prep + w2 prep (one launch) ------
__global__ void prep_all(const float* __restrict__ x,
                         const float* __restrict__ w1,
                         const float* __restrict__ w2) {
    int b = blockIdx.x;
    if (b < CVT_BLOCKS) {
        // ---- x -> (hi, lo) fp16 split, 16B stores ----
        size_t i = (size_t)b * 256 + threadIdx.x;
        size_t row = i / 98, g = i % 98;
        const float4* xp = (const float4*)(x + row * K_IN + g * 8);
        float4 v0 = xp[0], v1 = xp[1];
        float f[8] = {v0.x, v0.y, v0.z, v0.w, v1.x, v1.y, v1.z, v1.w};
        __half2 hi[4], lo[4];
        #pragma unroll
        for (int q = 0; q < 4; q++) {
            __half ha = __float2half(f[q * 2]), hb = __float2half(f[q * 2 + 1]);
            hi[q] = __halves2half2(ha, hb);
            lo[q] = __halves2half2(__float2half(f[q * 2]     - __half2float(ha)),
                                   __float2half(f[q * 2 + 1] - __half2float(hb)));
        }
        __half* base = g_Ah + row * KPAD;
        *(uint4*)(base + g * 8)       = *(uint4*)hi;
        *(uint4*)(base + 784 + g * 8) = *(uint4*)lo;
        if (g == 0) {
            uint4 z = {0, 0, 0, 0};
            #pragma unroll
            for (int q = 0; q < 4; q++) *(uint4*)(base + 1568 + q * 8) = z;
        }
    } else if (b < CVT_BLOCKS + N_H) {
        // ---- w1 row -> signs (duplicated) + alpha1 ----
        int n = b - CVT_BLOCKS;
        const float* row = w1 + n * K_IN;
        __half* brow = g_Bh + (size_t)n * KPAD;
        float s = 0.f;
        for (int k = threadIdx.x; k < K_IN; k += 256) {
            float w = row[k];
            s += fabsf(w);
            __half hs = __float2half(signf(w));
            brow[k] = hs;
            brow[784 + k] = hs;
        }
        if (threadIdx.x < 32) brow[1568 + threadIdx.x] = __float2half(0.f);
        __shared__ float red[256];
        red[threadIdx.x] = s;
        __syncthreads();
        for (int st = 128; st > 0; st >>= 1) {
            if (threadIdx.x < (unsigned)st) red[threadIdx.x] += red[threadIdx.x + st];
            __syncthreads();
        }
        if (threadIdx.x == 0) g_alpha1[n] = red[0] / (float)K_IN;
    } else {
        // ---- w2 prep: alpha2 + scaled signs ----
        __shared__ float a2[N_C];
        int wid = threadIdx.x >> 5, l = threadIdx.x & 31;
        for (int c = wid; c < N_C; c += 8) {
            float s = 0.f;
            for (int j = l; j < N_H; j += 32) s += fabsf(w2[c * N_H + j]);
            #pragma unroll
            for (int o = 16; o; o >>= 1) s += __shfl_down_sync(0xffffffffu, s, o);
            if (l == 0) a2[c] = s / (float)N_H;
        }
        __syncthreads();
        for (int idx = threadIdx.x; idx < N_C * N_H; idx += blockDim.x)
            g_s2a[idx] = a2[idx / N_H] * signf(w2[idx]);
    }
}

// ---------------- HMMA GEMM: d[B, H] = A @ Bh^T + fused BN partials ---------
// CTA 128x256, 512 threads (16 warps: 2 m-slabs x 8 n-slabs), warp tile 64x32.
// BK=32, 5-stage cp.async pipeline, ONE __syncthreads per chunk (R10 config).
__global__ __launch_bounds__(512, 1) void gemm1_mma() {
    extern __shared__ char dsm[];
    __half* Abuf = (__half*)dsm;                          // NSTAGE x 128 x 40
    __half* Bbuf = (__half*)(dsm + NSTAGE * A_STAGE_B);   // NSTAGE x 256 x 40

    const int tid  = threadIdx.x;
    const int lane = tid & 31;
    const int w    = tid >> 5;
    const int wm   = w & 1;          // 0..1 : 64-row slab
    const int wn   = w >> 1;         // 0..7 : 32-col slab
    const int bm   = blockIdx.y * BM;
    const int bn   = blockIdx.x * BN;

    float acc[4][4][4];
    #pragma unroll
    for (int i = 0; i < 4; i++)
        #pragma unroll
        for (int j = 0; j < 4; j++)
            #pragma unroll
            for (int q = 0; q < 4; q++) acc[i][j][q] = 0.f;

    // hoisted LDSM base addresses (stage 0, h = 0)
    uint32_t aAddr[4], bAddr[2];
    #pragma unroll
    for (int mi = 0; mi < 4; mi++)
        aAddr[mi] = smem_u32(Abuf + (wm * 64 + mi * 16 + (lane & 15)) * APITCH
                             + (lane >> 4) * 8);
    {
        int g = lane >> 3, r = lane & 7;
        #pragma unroll
        for (int jp = 0; jp < 2; jp++)
            bAddr[jp] = smem_u32(Bbuf + (wn * 32 + jp * 16 + ((g & 2) ? 8 : 0) + r)
                                 * APITCH + (g & 1) * 8);
    }

    // cp.async addressing: A 512 ops (1/thread), B 1024 ops (2/thread)
    const int a_row = tid >> 2;
    const int a_ck  = tid & 3;
    const uint32_t cpA = smem_u32(Abuf + a_row * APITCH + a_ck * 8);
    const int b_r0 = tid >> 2,          b_ck0 = tid & 3;
    const int b_r1 = (tid + 512) >> 2,  b_ck1 = tid & 3;
    const uint32_t cpB0 = smem_u32(Bbuf + b_r0 * APITCH + b_ck0 * 8);
    const uint32_t cpB1 = smem_u32(Bbuf + b_r1 * APITCH + b_ck1 * 8);
    const __half* gA = g_Ah + (size_t)(bm + a_row) * KPAD + a_ck * 8;
    const __half* gB0 = g_Bh + (size_t)(bn + b_r0) * KPAD + b_ck0 * 8;
    const __half* gB1 = g_Bh + (size_t)(bn + b_r1) * KPAD + b_ck1 * 8;

    auto prefetch = [&](int c, uint32_t sA, uint32_t sB) {
        if (c < NCHUNK) {
            const int k0 = c * BK;
            CP16(cpA + sA, gA + k0);
            CP16(cpB0 + sB, gB0 + k0);
            CP16(cpB1 + sB, gB1 + k0);
        }
        asm volatile("cp.async.commit_group;");
    };

    prefetch(0, 0, 0);
    prefetch(1, A_STAGE_B, B_STAGE_B);
    prefetch(2, 2 * A_STAGE_B, 2 * B_STAGE_B);
    prefetch(3, 3 * A_STAGE_B, 3 * B_STAGE_B);

    uint32_t sA = 0, sB = 0;                          // stage of chunk c
    uint32_t pA = 4 * A_STAGE_B, pB = 4 * B_STAGE_B;  // stage of chunk c+4

    for (int c = 0; c < NCHUNK; c++) {
        asm volatile("cp.async.wait_group 3;" ::: "memory");
        __syncthreads();

        // h0 fragments first so the first MMA's deps land earliest
        uint32_t afr[4][4];
        #pragma unroll
        for (int mi = 0; mi < 4; mi++) ldsm4(afr[mi], aAddr[mi] + sA);
        uint32_t bfr[2][4][2];
        #pragma unroll
        for (int jp = 0; jp < 2; jp++) {
            uint32_t rr[4];
            ldsm4(rr, bAddr[jp] + sB);
            bfr[0][jp * 2 + 0][0] = rr[0]; bfr[0][jp * 2 + 0][1] = rr[1];
            bfr[0][jp * 2 + 1][0] = rr[2]; bfr[0][jp * 2 + 1][1] = rr[3];
        }
        prefetch(c + 4, pA, pB);
        #pragma unroll
        for (int mi = 0; mi < 4; mi++)
            #pragma unroll
            for (int ni = 0; ni < 4; ni++)
                mma16816(acc[mi][ni], afr[mi], bfr[0][ni]);

        #pragma unroll
        for (int jp = 0; jp < 2; jp++) {
            uint32_t rr[4];
            ldsm4(rr, bAddr[jp] + sB + 32);
            bfr[1][jp * 2 + 0][0] = rr[0]; bfr[1][jp * 2 + 0][1] = rr[1];
            bfr[1][jp * 2 + 1][0] = rr[2]; bfr[1][jp * 2 + 1][1] = rr[3];
        }
        #pragma unroll
        for (int mi = 0; mi < 4; mi++) ldsm4(afr[mi], aAddr[mi] + sA + 32);
        #pragma unroll
        for (int mi = 0; mi < 4; mi++)
            #pragma unroll
            for (int ni = 0; ni < 4; ni++)
                mma16816(acc[mi][ni], afr[mi], bfr[1][ni]);

        // ring advance: both cursors move one stage per iteration
        sA += A_STAGE_B; if (sA == NSTAGE * A_STAGE_B) sA = 0;
        sB += B_STAGE_B; if (sB == NSTAGE * B_STAGE_B) sB = 0;
        pA += A_STAGE_B; if (pA == NSTAGE * A_STAGE_B) pA = 0;
        pB += B_STAGE_B; if (pB == NSTAGE * B_STAGE_B) pB = 0;
    }

    // ---- epilogue 1: store d tile (fp32) ---------------------------------
    float* base = g_d + (size_t)(bm + wm * 64) * N_H + bn + wn * 32;
    #pragma unroll
    for (int mi = 0; mi < 4; mi++) {
        #pragma unroll
        for (int ni = 0; ni < 4; ni++) {
            int r0  = mi * 16 + (lane >> 2);
            int col = ni * 8 + (lane & 3) * 2;
            float2 v0 = {acc[mi][ni][0], acc[mi][ni][1]};
            float2 v1 = {acc[mi][ni][2], acc[mi][ni][3]};
            *(float2*)(base + (size_t)r0 * N_H + col)       = v0;
            *(float2*)(base + (size_t)(r0 + 8) * N_H + col) = v1;
        }
    }

    // ---- epilogue 2: fused BN partial sums (deterministic) --------------
    float cs[8], cq[8];
    #pragma unroll
    for (int ni = 0; ni < 4; ni++) {
        #pragma unroll
        for (int q = 0; q < 2; q++) {
            float s = 0.f, sq = 0.f;
            #pragma unroll
            for (int mi = 0; mi < 4; mi++) {
                float v0 = acc[mi][ni][q], v1 = acc[mi][ni][q + 2];
                s += v0 + v1;
                sq = fmaf(v0, v0, sq);
                sq = fmaf(v1, v1, sq);
            }
            cs[ni * 2 + q] = s;
            cq[ni * 2 + q] = sq;
        }
    }
    #pragma unroll
    for (int o = 4; o <= 16; o <<= 1) {
        #pragma unroll
        for (int t = 0; t < 8; t++) {
            cs[t] += __shfl_xor_sync(0xffffffffu, cs[t], o);
            cq[t] += __shfl_xor_sync(0xffffffffu, cq[t], o);
        }
    }
    __syncthreads();                       // pipeline smem no longer needed
    float* sS = (float*)dsm;               // [2][256]
    float* sQ = sS + 512;                  // [2][256]
    if (lane < 4) {
        #pragma unroll
        for (int ni = 0; ni < 4; ni++) {
            #pragma unroll
            for (int q = 0; q < 2; q++) {
                int colL = wn * 32 + ni * 8 + lane * 2 + q;
                sS[wm * 256 + colL] = cs[ni * 2 + q];
                sQ[wm * 256 + colL] = cq[ni * 2 + q];
            }
        }
    }
    __syncthreads();
    if (tid < 256) {
        float s  = sS[tid] + sS[256 + tid];
        float sq = sQ[tid] + sQ[256 + tid];
        g_psum[(size_t)blockIdx.y * N_H + bn + tid] = s;
        g_psq [(size_t)blockIdx.y * N_H + bn + tid] = sq;
    }
}

// ---------------- BN stats finalize: one block per column -------------------
__global__ void stats_final(const float* __restrict__ gamma,
                            const float* __restrict__ beta) {
    int j = blockIdx.x;                       // 1024 blocks
    int t = threadIdx.x;                      // 128 threads
    __shared__ float rs[128], rq[128];
    float s = 0.f, q = 0.f;
    for (int p = t; p < NMB; p += 128) {      // fixed order -> deterministic
        s += g_psum[(size_t)p * N_H + j];
        q += g_psq [(size_t)p * N_H + j];
    }
    rs[t] = s; rq[t] = q;
    __syncthreads();
    for (int st = 64; st > 0; st >>= 1) {
        if (t < st) { rs[t] += rs[t + st]; rq[t] += rq[t + st]; }
        __syncthreads();
    }
    if (t == 0) {
        float inv = 1.f / (float)B_SZ;
        float mu  = rs[0] * inv;
        float var = rq[0] * inv - mu * mu;
        float a1  = g_alpha1[j];
        float r   = rsqrtf(a1 * a1 * var + BN_EPS);
        float c1  = gamma[j] * a1 * r;
        g_c1[j] = c1;
        g_c0[j] = beta[j] - c1 * mu;
    }
}

// ---------------- fused sign + GEMM2 (warp does 8 rows; 64 rows/block) ------
__global__ __launch_bounds__(256) void final_k(float* __restrict__ out) {
    __shared__ float s2[N_C][N_H];
    __shared__ float c1s[N_H];
    __shared__ float c0s[N_H];
    for (int i = threadIdx.x; i < N_C * N_H; i += 256) ((float*)s2)[i] = g_s2a[i];
    for (int i = threadIdx.x; i < N_H; i += 256) {
        c1s[i] = g_c1[i];
        c0s[i] = g_c0[i];
    }
    __syncthreads();

    int w = threadIdx.x >> 5, l = threadIdx.x & 31;
    #pragma unroll
    for (int r = 0; r < 8; r++) {
        int row = blockIdx.x * 64 + w * 8 + r;
        const float* dr = g_d + (size_t)row * N_H;

        float acc[N_C];
        #pragma unroll
        for (int c = 0; c < N_C; c++) acc[c] = 0.f;

        for (int g = 0; g < 32; g++) {
            int col = g * 32 + l;
            float v = dr[col];
            float s = c1s[col] * v + c0s[col];
            float a = (s > 0.f) ? 1.f : ((s < 0.f) ? -1.f : 0.f);
            #pragma unroll
            for (int c = 0; c < N_C; c++) acc[c] = fmaf(a, s2[c][col], acc[c]);
        }
        #pragma unroll
        for (int c = 0; c < N_C; c++) {
            float v = acc[c];
            #pragma unroll
            for (int o = 16; o; o >>= 1) v += __shfl_down_sync(0xffffffffu, v, o);
            if (l == 0) out[(size_t)row * N_C + c] = v;
        }
    }
}

// ---------------- launch -----------------------------------------------------
extern "C" void kernel_launch(void* const* d_in, const int* in_sizes, int n_in,
                              void* d_out, int out_size) {
    const float* x     = (const float*)d_in[0];
    const float* w1    = (const float*)d_in[1];
    const float* w2    = (const float*)d_in[2];
    const float* gamma = (const float*)d_in[3];
    const float* beta  = (const float*)d_in[4];
    float* out = (float*)d_out;

    cudaFuncSetAttribute(gemm1_mma, cudaFuncAttributeMaxDynamicSharedMemorySize,
                         SMEM_TOTAL);

    prep_all<<<PREP_BLOCKS, 256>>>(x, w1, w2);
    gemm1_mma<<<dim3(N_H / BN, B_SZ / BM), 512, SMEM_TOTAL>>>();
    stats_final<<<N_H, 128>>>(gamma, beta);
    final_k<<<B_SZ / 64, 256>>>(out);
}

// round 17
// speedup vs baseline: 1.0964x; 1.0821x over previous
#include <cuda_runtime.h>
#include <cuda_fp16.h>
#include <cstdint>

#define B_SZ 65536
#define K_IN 784
#define N_H  1024
#define N_C  10
#define BN_EPS 1e-5f

#define BM 128
#define BN 256
#define BK 32
#define KPAD 1600
#define NCHUNK (KPAD / BK)        // 50
#define APITCH 40                 // halves per smem row (32 + 8 pad)
#define NSTAGE 5

#define A_STAGE_B (BM * APITCH * 2)           // 10240
#define B_STAGE_B (BN * APITCH * 2)           // 20480
#define SMEM_TOTAL (NSTAGE * (A_STAGE_B + B_STAGE_B))   // 153600
#define NMB (B_SZ / BM)                       // 512 m-blocks

#define CVT_BLOCKS ((B_SZ * 98) / 256)        // 25088 convert blocks
#define PREP_BLOCKS (CVT_BLOCKS + N_H + 1)    // + w1 + w2

// ---------------- scratch (device globals; no runtime allocation) ----------
__device__ __half g_Ah[(size_t)B_SZ * KPAD];   // [B, 1600] = hi | lo | 0-pad
__device__ __half g_Bh[(size_t)N_H * KPAD];    // [H, 1600] = sign | sign | 0-pad
__device__ float  g_alpha1[N_H];
__device__ float  g_alpha2[N_C];
__device__ uint32_t g_w2bits[N_C * 32];        // bit l of word g = (w2[c][g*32+l] > 0)
__device__ float  g_d[(size_t)B_SZ * N_H];     // d = x @ sign(w1)^T (fp32)
__device__ float  g_psum[NMB * N_H];
__device__ float  g_psq [NMB * N_H];
__device__ float  g_c1[N_H];
__device__ float  g_c0[N_H];

// ---------------- PTX helpers (baseline ISA only) ----------------------------
__device__ __forceinline__ uint32_t smem_u32(const void* p) {
    uint32_t a;
    asm("{ .reg .u64 t; cvta.to.shared.u64 t, %1; cvt.u32.u64 %0, t; }"
        : "=r"(a) : "l"(p));
    return a;
}
#define CP16(sm, gm) \
    asm volatile("cp.async.cg.shared.global [%0], [%1], 16;" :: "r"(sm), "l"(gm))

__device__ __forceinline__ void ldsm4(uint32_t* r, uint32_t addr) {
    asm volatile("ldmatrix.sync.aligned.m8n8.x4.shared.b16 {%0,%1,%2,%3}, [%4];"
                 : "=r"(r[0]), "=r"(r[1]), "=r"(r[2]), "=r"(r[3]) : "r"(addr));
}
__device__ __forceinline__ void mma16816(float* d, const uint32_t* a,
                                         const uint32_t* b) {
    asm volatile(
        "mma.sync.aligned.m16n8k16.row.col.f32.f16.f16.f32 "
        "{%0,%1,%2,%3}, {%4,%5,%6,%7}, {%8,%9}, {%0,%1,%2,%3};"
        : "+f"(d[0]), "+f"(d[1]), "+f"(d[2]), "+f"(d[3])
        : "r"(a[0]), "r"(a[1]), "r"(a[2]), "r"(a[3]), "r"(b[0]), "r"(b[1]));
}

__device__ __forceinline__ float signf(float w) {
    return (w > 0.f) ? 1.f : ((w < 0.f) ? -1.f : 0.f);
}

// ---------------- fused prep: x split + w1 prep + w2 prep (one launch) ------
__global__ void prep_all(const float* __restrict__ x,
                         const float* __restrict__ w1,
                         const float* __restrict__ w2) {
    int b = blockIdx.x;
    if (b < CVT_BLOCKS) {
        // ---- x -> (hi, lo) fp16 split, 16B stores ----
        size_t i = (size_t)b * 256 + threadIdx.x;
        size_t row = i / 98, g = i % 98;
        const float4* xp = (const float4*)(x + row * K_IN + g * 8);
        float4 v0 = xp[0], v1 = xp[1];
        float f[8] = {v0.x, v0.y, v0.z, v0.w, v1.x, v1.y, v1.z, v1.w};
        __half2 hi[4], lo[4];
        #pragma unroll
        for (int q = 0; q < 4; q++) {
            __half ha = __float2half(f[q * 2]), hb = __float2half(f[q * 2 + 1]);
            hi[q] = __halves2half2(ha, hb);
            lo[q] = __halves2half2(__float2half(f[q * 2]     - __half2float(ha)),
                                   __float2half(f[q * 2 + 1] - __half2float(hb)));
        }
        __half* base = g_Ah + row * KPAD;
        *(uint4*)(base + g * 8)       = *(uint4*)hi;
        *(uint4*)(base + 784 + g * 8) = *(uint4*)lo;
        if (g == 0) {
            uint4 z = {0, 0, 0, 0};
            #pragma unroll
            for (int q = 0; q < 4; q++) *(uint4*)(base + 1568 + q * 8) = z;
        }
    } else if (b < CVT_BLOCKS + N_H) {
        // ---- w1 row -> signs (duplicated) + alpha1 ----
        int n = b - CVT_BLOCKS;
        const float* row = w1 + n * K_IN;
        __half* brow = g_Bh + (size_t)n * KPAD;
        float s = 0.f;
        for (int k = threadIdx.x; k < K_IN; k += 256) {
            float w = row[k];
            s += fabsf(w);
            __half hs = __float2half(signf(w));
            brow[k] = hs;
            brow[784 + k] = hs;
        }
        if (threadIdx.x < 32) brow[1568 + threadIdx.x] = __float2half(0.f);
        __shared__ float red[256];
        red[threadIdx.x] = s;
        __syncthreads();
        for (int st = 128; st > 0; st >>= 1) {
            if (threadIdx.x < (unsigned)st) red[threadIdx.x] += red[threadIdx.x + st];
            __syncthreads();
        }
        if (threadIdx.x == 0) g_alpha1[n] = red[0] / (float)K_IN;
    } else {
        // ---- w2 prep: alpha2 + packed sign bits ----
        int wid = threadIdx.x >> 5, l = threadIdx.x & 31;
        for (int c = wid; c < N_C; c += 8) {
            float s = 0.f;
            #pragma unroll
            for (int g = 0; g < 32; g++) {
                float wv = w2[c * N_H + g * 32 + l];
                s += fabsf(wv);
                uint32_t m = __ballot_sync(0xffffffffu, wv > 0.f);
                if (l == 0) g_w2bits[c * 32 + g] = m;
            }
            #pragma unroll
            for (int o = 16; o; o >>= 1) s += __shfl_down_sync(0xffffffffu, s, o);
            if (l == 0) g_alpha2[c] = s / (float)N_H;
        }
    }
}

// ---------------- HMMA GEMM: d[B, H] = A @ Bh^T + fused BN partials ---------
// CTA 128x256, 512 threads (16 warps: 2 m-slabs x 8 n-slabs), warp tile 64x32.
// BK=32, 5-stage cp.async pipeline, ONE __syncthreads per chunk (R10 config).
__global__ __launch_bounds__(512, 1) void gemm1_mma() {
    extern __shared__ char dsm[];
    __half* Abuf = (__half*)dsm;                          // NSTAGE x 128 x 40
    __half* Bbuf = (__half*)(dsm + NSTAGE * A_STAGE_B);   // NSTAGE x 256 x 40

    const int tid  = threadIdx.x;
    const int lane = tid & 31;
    const int w    = tid >> 5;
    const int wm   = w & 1;          // 0..1 : 64-row slab
    const int wn   = w >> 1;         // 0..7 : 32-col slab
    const int bm   = blockIdx.y * BM;
    const int bn   = blockIdx.x * BN;

    float acc[4][4][4];
    #pragma unroll
    for (int i = 0; i < 4; i++)
        #pragma unroll
        for (int j = 0; j < 4; j++)
            #pragma unroll
            for (int q = 0; q < 4; q++) acc[i][j][q] = 0.f;

    // hoisted LDSM base addresses (stage 0, h = 0)
    uint32_t aAddr[4], bAddr[2];
    #pragma unroll
    for (int mi = 0; mi < 4; mi++)
        aAddr[mi] = smem_u32(Abuf + (wm * 64 + mi * 16 + (lane & 15)) * APITCH
                             + (lane >> 4) * 8);
    {
        int g = lane >> 3, r = lane & 7;
        #pragma unroll
        for (int jp = 0; jp < 2; jp++)
            bAddr[jp] = smem_u32(Bbuf + (wn * 32 + jp * 16 + ((g & 2) ? 8 : 0) + r)
                                 * APITCH + (g & 1) * 8);
    }

    // cp.async addressing: A 512 ops (1/thread), B 1024 ops (2/thread)
    const int a_row = tid >> 2;
    const int a_ck  = tid & 3;
    const uint32_t cpA = smem_u32(Abuf + a_row * APITCH + a_ck * 8);
    const int b_r0 = tid >> 2,          b_ck0 = tid & 3;
    const int b_r1 = (tid + 512) >> 2,  b_ck1 = tid & 3;
    const uint32_t cpB0 = smem_u32(Bbuf + b_r0 * APITCH + b_ck0 * 8);
    const uint32_t cpB1 = smem_u32(Bbuf + b_r1 * APITCH + b_ck1 * 8);
    const __half* gA = g_Ah + (size_t)(bm + a_row) * KPAD + a_ck * 8;
    const __half* gB0 = g_Bh + (size_t)(bn + b_r0) * KPAD + b_ck0 * 8;
    const __half* gB1 = g_Bh + (size_t)(bn + b_r1) * KPAD + b_ck1 * 8;

    auto prefetch = [&](int c, uint32_t sA, uint32_t sB) {
        if (c < NCHUNK) {
            const int k0 = c * BK;
            CP16(cpA + sA, gA + k0);
            CP16(cpB0 + sB, gB0 + k0);
            CP16(cpB1 + sB, gB1 + k0);
        }
        asm volatile("cp.async.commit_group;");
    };

    prefetch(0, 0, 0);
    prefetch(1, A_STAGE_B, B_STAGE_B);
    prefetch(2, 2 * A_STAGE_B, 2 * B_STAGE_B);
    prefetch(3, 3 * A_STAGE_B, 3 * B_STAGE_B);

    uint32_t sA = 0, sB = 0;                          // stage of chunk c
    uint32_t pA = 4 * A_STAGE_B, pB = 4 * B_STAGE_B;  // stage of chunk c+4

    for (int c = 0; c < NCHUNK; c++) {
        asm volatile("cp.async.wait_group 3;" ::: "memory");
        __syncthreads();

        // h0 fragments first so the first MMA's deps land earliest
        uint32_t afr[4][4];
        #pragma unroll
        for (int mi = 0; mi < 4; mi++) ldsm4(afr[mi], aAddr[mi] + sA);
        uint32_t bfr[2][4][2];
        #pragma unroll
        for (int jp = 0; jp < 2; jp++) {
            uint32_t rr[4];
            ldsm4(rr, bAddr[jp] + sB);
            bfr[0][jp * 2 + 0][0] = rr[0]; bfr[0][jp * 2 + 0][1] = rr[1];
            bfr[0][jp * 2 + 1][0] = rr[2]; bfr[0][jp * 2 + 1][1] = rr[3];
        }
        prefetch(c + 4, pA, pB);
        #pragma unroll
        for (int mi = 0; mi < 4; mi++)
            #pragma unroll
            for (int ni = 0; ni < 4; ni++)
                mma16816(acc[mi][ni], afr[mi], bfr[0][ni]);

        #pragma unroll
        for (int jp = 0; jp < 2; jp++) {
            uint32_t rr[4];
            ldsm4(rr, bAddr[jp] + sB + 32);
            bfr[1][jp * 2 + 0][0] = rr[0]; bfr[1][jp * 2 + 0][1] = rr[1];
            bfr[1][jp * 2 + 1][0] = rr[2]; bfr[1][jp * 2 + 1][1] = rr[3];
        }
        #pragma unroll
        for (int mi = 0; mi < 4; mi++) ldsm4(afr[mi], aAddr[mi] + sA + 32);
        #pragma unroll
        for (int mi = 0; mi < 4; mi++)
            #pragma unroll
            for (int ni = 0; ni < 4; ni++)
                mma16816(acc[mi][ni], afr[mi], bfr[1][ni]);

        // ring advance: both cursors move one stage per iteration
        sA += A_STAGE_B; if (sA == NSTAGE * A_STAGE_B) sA = 0;
        sB += B_STAGE_B; if (sB == NSTAGE * B_STAGE_B) sB = 0;
        pA += A_STAGE_B; if (pA == NSTAGE * A_STAGE_B) pA = 0;
        pB += B_STAGE_B; if (pB == NSTAGE * B_STAGE_B) pB = 0;
    }

    // ---- epilogue 1: store d tile (fp32) ---------------------------------
    float* base = g_d + (size_t)(bm + wm * 64) * N_H + bn + wn * 32;
    #pragma unroll
    for (int mi = 0; mi < 4; mi++) {
        #pragma unroll
        for (int ni = 0; ni < 4; ni++) {
            int r0  = mi * 16 + (lane >> 2);
            int col = ni * 8 + (lane & 3) * 2;
            float2 v0 = {acc[mi][ni][0], acc[mi][ni][1]};
            float2 v1 = {acc[mi][ni][2], acc[mi][ni][3]};
            *(float2*)(base + (size_t)r0 * N_H + col)       = v0;
            *(float2*)(base + (size_t)(r0 + 8) * N_H + col) = v1;
        }
    }

    // ---- epilogue 2: fused BN partial sums (deterministic) --------------
    float cs[8], cq[8];
    #pragma unroll
    for (int ni = 0; ni < 4; ni++) {
        #pragma unroll
        for (int q = 0; q < 2; q++) {
            float s = 0.f, sq = 0.f;
            #pragma unroll
            for (int mi = 0; mi < 4; mi++) {
                float v0 = acc[mi][ni][q], v1 = acc[mi][ni][q + 2];
                s += v0 + v1;
                sq = fmaf(v0, v0, sq);
                sq = fmaf(v1, v1, sq);
            }
            cs[ni * 2 + q] = s;
            cq[ni * 2 + q] = sq;
        }
    }
    #pragma unroll
    for (int o = 4; o <= 16; o <<= 1) {
        #pragma unroll
        for (int t = 0; t < 8; t++) {
            cs[t] += __shfl_xor_sync(0xffffffffu, cs[t], o);
            cq[t] += __shfl_xor_sync(0xffffffffu, cq[t], o);
        }
    }
    __syncthreads();                       // pipeline smem no longer needed
    float* sS = (float*)dsm;               // [2][256]
    float* sQ = sS + 512;                  // [2][256]
    if (lane < 4) {
        #pragma unroll
        for (int ni = 0; ni < 4; ni++) {
            #pragma unroll
            for (int q = 0; q < 2; q++) {
                int colL = wn * 32 + ni * 8 + lane * 2 + q;
                sS[wm * 256 + colL] = cs[ni * 2 + q];
                sQ[wm * 256 + colL] = cq[ni * 2 + q];
            }
        }
    }
    __syncthreads();
    if (tid < 256) {
        float s  = sS[tid] + sS[256 + tid];
        float sq = sQ[tid] + sQ[256 + tid];
        g_psum[(size_t)blockIdx.y * N_H + bn + tid] = s;
        g_psq [(size_t)blockIdx.y * N_H + bn + tid] = sq;
    }
}

// ---------------- BN stats finalize: one block per column -------------------
__global__ void stats_final(const float* __restrict__ gamma,
                            const float* __restrict__ beta) {
    int j = blockIdx.x;                       // 1024 blocks
    int t = threadIdx.x;                      // 128 threads
    __shared__ float rs[128], rq[128];
    float s = 0.f, q = 0.f;
    for (int p = t; p < NMB; p += 128) {      // fixed order -> deterministic
        s += g_psum[(size_t)p * N_H + j];
        q += g_psq [(size_t)p * N_H + j];
    }
    rs[t] = s; rq[t] = q;
    __syncthreads();
    for (int st = 64; st > 0; st >>= 1) {
        if (t < st) { rs[t] += rs[t + st]; rq[t] += rq[t + st]; }
        __syncthreads();
    }
    if (t == 0) {
        float inv = 1.f / (float)B_SZ;
        float mu  = rs[0] * inv;
        float var = rq[0] * inv - mu * mu;
        float a1  = g_alpha1[j];
        float r   = rsqrtf(a1 * a1 * var + BN_EPS);
        float c1  = gamma[j] * a1 * r;
        g_c1[j] = c1;
        g_c0[j] = beta[j] - c1 * mu;
    }
}

// ---------------- fused sign + binary GEMM2 (ballot + popcount) -------------
// warp per row (8 rows each), out[c] = alpha2[c] * (1024 - 2*popc_mismatch)
__global__ __launch_bounds__(256) void final_k(float* __restrict__ out) {
    __shared__ float c1s[N_H];
    __shared__ float c0s[N_H];
    __shared__ uint32_t wb[N_C * 32];
    __shared__ float a2s[N_C];
    for (int i = threadIdx.x; i < N_H; i += 256) {
        c1s[i] = g_c1[i];
        c0s[i] = g_c0[i];
    }
    for (int i = threadIdx.x; i < N_C * 32; i += 256) wb[i] = g_w2bits[i];
    if (threadIdx.x < N_C) a2s[threadIdx.x] = g_alpha2[threadIdx.x];
    __syncthreads();

    int w = threadIdx.x >> 5, l = threadIdx.x & 31;
    // lane c < 10 owns class c; preload its 32 weight words into registers
    uint32_t myw[32];
    if (l < N_C) {
        #pragma unroll
        for (int g = 0; g < 32; g++) myw[g] = wb[l * 32 + g];
    }

    #pragma unroll
    for (int r = 0; r < 8; r++) {
        int row = blockIdx.x * 64 + w * 8 + r;
        const float* dr = g_d + (size_t)row * N_H;

        int xsum = 0;
        #pragma unroll
        for (int g = 0; g < 32; g++) {
            int col = g * 32 + l;
            float s = fmaf(c1s[col], dr[col], c0s[col]);
            uint32_t m = __ballot_sync(0xffffffffu, s > 0.f);
            if (l < N_C) xsum += __popc(m ^ myw[g]);
        }
        if (l < N_C)
            out[(size_t)row * N_C + l] = a2s[l] * (float)(N_H - 2 * xsum);
    }
}

// ---------------- launch -----------------------------------------------------
extern "C" void kernel_launch(void* const* d_in, const int* in_sizes, int n_in,
                              void* d_out, int out_size) {
    const float* x     = (const float*)d_in[0];
    const float* w1    = (const float*)d_in[1];
    const float* w2    = (const float*)d_in[2];
    const float* gamma = (const float*)d_in[3];
    const float* beta  = (const float*)d_in[4];
    float* out = (float*)d_out;

    cudaFuncSetAttribute(gemm1_mma, cudaFuncAttributeMaxDynamicSharedMemorySize,
                         SMEM_TOTAL);

    prep_all<<<PREP_BLOCKS, 256>>>(x, w1, w2);
    gemm1_mma<<<dim3(N_H / BN, B_SZ / BM), 512, SMEM_TOTAL>>>();
    stats_final<<<N_H, 128>>>(gamma, beta);
    final_k<<<B_SZ / 64, 256>>>(out);
}